// round 7
// baseline (speedup 1.0000x reference)
#include <cuda_runtime.h>
#include <math.h>

// Problem constants
#define B_ 256
#define T_ 128
#define D_ 256
#define U_ 512
#define G5 2560   // 5*U
#define G4 2048   // 4*U
#define G3 1536   // 3*U

#define NBLK 128
#define NTHR 256
#define KT 32
#define ASLP 34        // A dup-pair stride per kk (pairs); even => 16B-aligned rows
#define BSL 36         // B float stride per (kk,gate)

// Scratch (device globals: allocation-free per harness rules)
__device__ float g_xg[(long)B_ * T_ * G5]; // precomputed x@kernel + input_bias
__device__ float g_h [B_ * U_];            // recurrent state h
__device__ float g_h1a[B_ * U_];           // ping
__device__ float g_h1b[B_ * U_];           // pong
__device__ unsigned g_bar_ctr;             // grid barrier counter

__device__ __forceinline__ float hsig(float x) {
    return fminf(fmaxf(0.2f * x + 0.5f, 0.0f), 1.0f);
}

// packed f32x2 helpers (Blackwell double-pumped fp32)
__device__ __forceinline__ unsigned long long pk(float x) {
    unsigned long long r;
    asm("mov.b64 %0, {%1, %1};" : "=l"(r) : "f"(x));
    return r;
}
__device__ __forceinline__ unsigned long long f2(unsigned long long a,
                                                 unsigned long long b,
                                                 unsigned long long c) {
    unsigned long long d;
    asm("fma.rn.f32x2 %0, %1, %2, %3;" : "=l"(d) : "l"(a), "l"(b), "l"(c));
    return d;
}
__device__ __forceinline__ float2 up(unsigned long long v) {
    float2 r;
    asm("mov.b64 {%0, %1}, %2;" : "=f"(r.x), "=f"(r.y) : "l"(v));
    return r;
}

// ---------------------------------------------------------------------------
__global__ void init_h_kernel(const float* __restrict__ h0) {
    int i = blockIdx.x * blockDim.x + threadIdx.x;
    if (i < B_ * U_) g_h[i] = h0[i];
    if (i == 0) g_bar_ctr = 0;
}

// ---------------------------------------------------------------------------
// xg = x @ kernel + bias[0], f32x2 with duplicated-A shared layout.
// 128x128x8 tiles, 256 threads, thread tile 8m x 8n (4 n-pairs).
// ---------------------------------------------------------------------------
#define XASL 130   // pair stride per k row (even)
__global__ void __launch_bounds__(256)
xg_gemm_kernel(const float* __restrict__ X,
               const float* __restrict__ W,
               const float* __restrict__ bias) {
    __shared__ float As2[8 * XASL * 2];  // dup pairs [k][m]
    __shared__ float Bs[8 * 128];        // [k][n]
    const int bm = blockIdx.y * 128;
    const int bn = blockIdx.x * 128;
    const int tid = threadIdx.x;
    const int tx = tid & 15, ty = tid >> 4;
    const int arow = tid >> 1, acol = (tid & 1) * 4;
    const int brow = tid >> 5, bcol = (tid & 31) * 4;

    unsigned long long acc[8][4];
#pragma unroll
    for (int i = 0; i < 8; i++)
#pragma unroll
        for (int j = 0; j < 4; j++) acc[i][j] = 0ull;

    const float* Xp = X + (bm + arow) * D_ + acol;
    const float* Wp = W + brow * G5 + bn + bcol;

    for (int k0 = 0; k0 < D_; k0 += 8) {
        float4 av = *(const float4*)(Xp + k0);
        *(unsigned long long*)(As2 + ((acol + 0) * XASL + arow) * 2) = pk(av.x);
        *(unsigned long long*)(As2 + ((acol + 1) * XASL + arow) * 2) = pk(av.y);
        *(unsigned long long*)(As2 + ((acol + 2) * XASL + arow) * 2) = pk(av.z);
        *(unsigned long long*)(As2 + ((acol + 3) * XASL + arow) * 2) = pk(av.w);
        *(float4*)&Bs[brow * 128 + bcol] = *(const float4*)(Wp + (long)k0 * G5);
        __syncthreads();
#pragma unroll
        for (int k = 0; k < 8; k++) {
            const ulonglong2* ap =
                (const ulonglong2*)(As2 + (k * XASL + ty * 8) * 2);
            ulonglong2 a01 = ap[0], a23 = ap[1], a45 = ap[2], a67 = ap[3];
            unsigned long long a[8] = {a01.x, a01.y, a23.x, a23.y,
                                       a45.x, a45.y, a67.x, a67.y};
            const ulonglong2* bp =
                (const ulonglong2*)(Bs + k * 128 + tx * 8);
            ulonglong2 b01 = bp[0], b23 = bp[1];
            unsigned long long b[4] = {b01.x, b01.y, b23.x, b23.y};
#pragma unroll
            for (int i = 0; i < 8; i++)
#pragma unroll
                for (int j = 0; j < 4; j++) acc[i][j] = f2(a[i], b[j], acc[i][j]);
        }
        __syncthreads();
    }

#pragma unroll
    for (int i = 0; i < 8; i++) {
        int m = bm + ty * 8 + i;
        float* o = g_xg + (long)m * G5 + bn + tx * 8;
#pragma unroll
        for (int j = 0; j < 4; j++) {
            float2 v = up(acc[i][j]);
            o[2 * j]     = v.x + bias[bn + tx * 8 + 2 * j];
            o[2 * j + 1] = v.y + bias[bn + tx * 8 + 2 * j + 1];
        }
    }
}

// ---------------------------------------------------------------------------
// Grid-wide barrier: release-arrive + acquire-spin (CG grid.sync pattern).
// ---------------------------------------------------------------------------
__device__ __forceinline__ void grid_bar(unsigned target) {
    __syncthreads();
    if (threadIdx.x == 0) {
        asm volatile("red.release.gpu.global.add.u32 [%0], %1;"
                     :: "l"(&g_bar_ctr), "r"(1u) : "memory");
        unsigned v;
        do {
            asm volatile("ld.acquire.gpu.global.u32 %0, [%1];"
                         : "=r"(v) : "l"(&g_bar_ctr) : "memory");
        } while (v < target);
    }
    __syncthreads();
}

// ---------------------------------------------------------------------------
// Fused tile GEMM: block computes 32m x (G gates x 32u) of  Asrc @ W.
// 256 threads. Thread (mIdx = tid>>4 in 0..15, uIdx = tid&15) owns
// 2m x (G x 2u): acc[g*2+i] packed f32x2 over the u-pair, i = m sub-row.
// A is staged in shared as duplicated {v,v} pairs so the hot loop has zero
// packing MOVs: 1 LDS.128 (two dup A pairs) + G LDS.64 (B pairs) + 2G FFMA2.
// ---------------------------------------------------------------------------
template <int G>
__device__ __forceinline__ void mm_tile(float* As2, float* Bs,
                                        const float* __restrict__ Asrc,
                                        const float* __restrict__ W, int ldw,
                                        int m0, int u0,
                                        unsigned long long* acc) {
    const int tid  = threadIdx.x;
    const int uIdx = tid & 15;
    const int mIdx = tid >> 4;
    const int mA   = tid >> 3;        // A loader: row 0..31
    const int kA   = (tid & 7) * 4;   // A loader: k offset 0..28 step 4

#pragma unroll
    for (int i = 0; i < 2 * G; i++) acc[i] = 0ull;

    // B loader coordinates: G float4 per thread, tile KT x (G x 32u)
    int  bso[G];
    long bgo[G];
#pragma unroll
    for (int r = 0; r < G; r++) {
        int fi  = tid + r * NTHR;
        int kk  = fi / (8 * G);
        int rem = fi - kk * 8 * G;
        int g   = rem >> 3;
        int u4  = (rem & 7) * 4;
        bso[r] = (kk * G + g) * BSL + u4;
        bgo[r] = (long)kk * ldw + g * U_ + u0 + u4;
    }
    const float* Ap = Asrc + (m0 + mA) * U_ + kA;

    // prefetch first tile
    float4 pa = __ldcg((const float4*)(Ap));
    float4 pb[G];
#pragma unroll
    for (int r = 0; r < G; r++)
        pb[r] = __ldg((const float4*)(W + bgo[r]));

    for (int k0 = 0; k0 < U_; k0 += KT) {
        __syncthreads();
        *(unsigned long long*)(As2 + ((kA + 0) * ASLP + mA) * 2) = pk(pa.x);
        *(unsigned long long*)(As2 + ((kA + 1) * ASLP + mA) * 2) = pk(pa.y);
        *(unsigned long long*)(As2 + ((kA + 2) * ASLP + mA) * 2) = pk(pa.z);
        *(unsigned long long*)(As2 + ((kA + 3) * ASLP + mA) * 2) = pk(pa.w);
#pragma unroll
        for (int r = 0; r < G; r++)
            *(float4*)(Bs + bso[r]) = pb[r];
        __syncthreads();
        if (k0 + KT < U_) {
            pa = __ldcg((const float4*)(Ap + k0 + KT));
#pragma unroll
            for (int r = 0; r < G; r++)
                pb[r] = __ldg((const float4*)(W + (long)(k0 + KT) * ldw + bgo[r]));
        }
#pragma unroll 8
        for (int kk = 0; kk < KT; kk++) {
            // two duplicated A pairs (m = 2*mIdx, 2*mIdx+1) in one LDS.128
            ulonglong2 av = *(const ulonglong2*)(As2 + (kk * ASLP + 2 * mIdx) * 2);
            const float* Bk = Bs + kk * G * BSL + 2 * uIdx;
#pragma unroll
            for (int g = 0; g < G; g++) {
                unsigned long long bg = *(const unsigned long long*)(Bk + g * BSL);
                acc[g * 2 + 0] = f2(av.x, bg, acc[g * 2 + 0]);
                acc[g * 2 + 1] = f2(av.y, bg, acc[g * 2 + 1]);
            }
        }
    }
}

// ---------------------------------------------------------------------------
// Persistent scan kernel: 128 blocks x 256 threads, whole T=128 scan.
// Block (u0, m0) owns the same 32m x 32u output tile in every phase.
// ---------------------------------------------------------------------------
__global__ void __launch_bounds__(NTHR)
scan_kernel(const float* __restrict__ Wr, const float* __restrict__ Wt,
            const float* __restrict__ bias, const float* __restrict__ tbias,
            float* __restrict__ out) {
    __shared__ float As2[KT * ASLP * 2];   // dup pairs
    __shared__ float Bs[KT * 4 * BSL];

    const int u0   = (blockIdx.x & 15) * 32;
    const int m0   = (blockIdx.x >> 4) * 32;
    const int tid  = threadIdx.x;
    const int uIdx = tid & 15;
    const int mIdx = tid >> 4;

    unsigned barno = 0;
    unsigned long long acc[8];
    float h1r[2][2];   // h1 carried rec -> t0 -> t1 (own 2m x 2u tile)
    float hlr[2][2];   // hl carried rec -> t1

    for (int t = 0; t < T_; t++) {
        // ---- phase REC: hg = h @ Wr (4 gates) ----
        mm_tile<4>(As2, Bs, g_h, Wr, G4, m0, u0, acc);
#pragma unroll
        for (int i = 0; i < 2; i++) {
            const int b = m0 + mIdx * 2 + i;
            const float* xp = g_xg + ((long)b * T_ + t) * G5;
            float2 pz = up(acc[0 + i]), pr = up(acc[2 + i]);
            float2 ph = up(acc[4 + i]), pl = up(acc[6 + i]);
#pragma unroll
            for (int h2 = 0; h2 < 2; h2++) {
                const int u = u0 + uIdx * 2 + h2;
                float az = h2 ? pz.y : pz.x;
                float ar = h2 ? pr.y : pr.x;
                float ah = h2 ? ph.y : ph.x;
                float al = h2 ? pl.y : pl.x;
                float z  = hsig(__ldg(xp + u) + az + __ldg(bias + G5 + u));
                float r  = hsig(__ldg(xp + U_ + u) + ar + __ldg(bias + G5 + U_ + u));
                float hh = tanhf(__ldg(xp + 2 * U_ + u) +
                                 r * (ah + __ldg(bias + G5 + 2 * U_ + u)));
                float hold = __ldcg(g_h + (long)b * U_ + u);
                float h1 = z * hold + (1.0f - z) * hh;
                __stcg(g_h1a + (long)b * U_ + u, h1);
                h1r[i][h2] = h1;
                hlr[i][h2] = al + __ldg(bias + G5 + 3 * U_ + u);
            }
        }
        grid_bar(++barno * NBLK);

        // ---- phase T0: tg = h1 @ Wt[0] (3 gates) ----
        mm_tile<3>(As2, Bs, g_h1a, Wt, G3, m0, u0, acc);
#pragma unroll
        for (int i = 0; i < 2; i++) {
            const int b = m0 + mIdx * 2 + i;
            float2 pz = up(acc[0 + i]), pr = up(acc[2 + i]), ph = up(acc[4 + i]);
#pragma unroll
            for (int h2 = 0; h2 < 2; h2++) {
                const int u = u0 + uIdx * 2 + h2;
                float az = h2 ? pz.y : pz.x;
                float ar = h2 ? pr.y : pr.x;
                float ah = h2 ? ph.y : ph.x;
                float zt = hsig(az + __ldg(tbias + u));
                float rt = hsig(ar + __ldg(tbias + U_ + u));
                float ht = tanhf(rt * (ah + __ldg(tbias + 2 * U_ + u)));
                float h1 = zt * h1r[i][h2] + (1.0f - zt) * ht;
                __stcg(g_h1b + (long)b * U_ + u, h1);
                h1r[i][h2] = h1;
            }
        }
        grid_bar(++barno * NBLK);

        // ---- phase T1: tg = h1 @ Wt[1] (3 gates), final combine ----
        mm_tile<3>(As2, Bs, g_h1b, Wt + (long)U_ * G3, G3, m0, u0, acc);
#pragma unroll
        for (int i = 0; i < 2; i++) {
            const int b = m0 + mIdx * 2 + i;
            const float* xp = g_xg + ((long)b * T_ + t) * G5;
            float2 pz = up(acc[0 + i]), pr = up(acc[2 + i]), ph = up(acc[4 + i]);
#pragma unroll
            for (int h2 = 0; h2 < 2; h2++) {
                const int u = u0 + uIdx * 2 + h2;
                float az = h2 ? pz.y : pz.x;
                float ar = h2 ? pr.y : pr.x;
                float ah = h2 ? ph.y : ph.x;
                float zt = hsig(az + __ldg(tbias + G3 + u));
                float rt = hsig(ar + __ldg(tbias + G3 + U_ + u));
                float ht = tanhf(rt * (ah + __ldg(tbias + G3 + 2 * U_ + u)));
                float h1 = zt * h1r[i][h2] + (1.0f - zt) * ht;
                float l  = hsig(__ldg(xp + 3 * U_ + u) + hlr[i][h2]);
                float ho = l * h1 + (1.0f - l) * tanhf(__ldg(xp + 4 * U_ + u));
                __stcg(g_h + (long)b * U_ + u, ho);
                out[((long)b * T_ + t) * U_ + u] = ho;
            }
        }
        grid_bar(++barno * NBLK);
    }
}

// ---------------------------------------------------------------------------
extern "C" void kernel_launch(void* const* d_in, const int* in_sizes, int n_in,
                              void* d_out, int out_size) {
    (void)in_sizes; (void)n_in; (void)out_size;
    const float* x      = (const float*)d_in[0];
    const float* h0     = (const float*)d_in[1];
    const float* kernel = (const float*)d_in[2];
    const float* Wr     = (const float*)d_in[3];
    const float* Wt     = (const float*)d_in[4];   // (2, 512, 1536)
    const float* bias   = (const float*)d_in[5];   // (2, 2560)
    const float* tbias  = (const float*)d_in[6];   // (2, 1536)
    float* out = (float*)d_out;

    init_h_kernel<<<(B_ * U_ + 255) / 256, 256>>>(h0);
    xg_gemm_kernel<<<dim3(G5 / 128, (B_ * T_) / 128), 256>>>(x, kernel, bias);
    scan_kernel<<<NBLK, NTHR>>>(Wr, Wt, bias, tbias, out);
}

// round 8
// speedup vs baseline: 1.3974x; 1.3974x over previous
#include <cuda_runtime.h>
#include <math.h>

// Problem constants
#define B_ 256
#define T_ 128
#define D_ 256
#define U_ 512
#define G5 2560   // 5*U
#define G4 2048   // 4*U
#define G3 1536   // 3*U

#define NBLK 128
#define NTHR 128          // scan threads per block
#define KT 32
#define ASL 33            // A smem stride (floats) per kk row; scalar reads
#define BSL 32            // B smem stride per (kk,gate): exactly 128B, aligned

// Scratch (device globals: allocation-free per harness rules)
__device__ float g_xg[(long)B_ * T_ * G5];
__device__ float g_h [B_ * U_];
__device__ float g_h1a[B_ * U_];
__device__ float g_h1b[B_ * U_];
__device__ unsigned g_bar_ctr;

__device__ __forceinline__ float hsig(float x) {
    return fminf(fmaxf(0.2f * x + 0.5f, 0.0f), 1.0f);
}

typedef unsigned long long ull;
__device__ __forceinline__ ull pk(float x) {
    ull r; asm("mov.b64 %0, {%1, %1};" : "=l"(r) : "f"(x)); return r;
}
__device__ __forceinline__ ull f2(ull a, ull b, ull c) {
    ull d; asm("fma.rn.f32x2 %0, %1, %2, %3;" : "=l"(d) : "l"(a), "l"(b), "l"(c));
    return d;
}
__device__ __forceinline__ float2 up(ull v) {
    float2 r; asm("mov.b64 {%0, %1}, %2;" : "=f"(r.x), "=f"(r.y) : "l"(v));
    return r;
}

// ---------------------------------------------------------------------------
__global__ void init_h_kernel(const float* __restrict__ h0) {
    int i = blockIdx.x * blockDim.x + threadIdx.x;
    if (i < B_ * U_) g_h[i] = h0[i];
    if (i == 0) g_bar_ctr = 0;
}

// ---------------------------------------------------------------------------
// xg = x @ kernel + bias[0].  f32x2, broadcast-oriented smem reads.
// 256 thr, tile 128m x 128n x 8k. Warp = 4 mG x 8 nG; 8 warps = 4 mW x 2 nW.
// Thread owns 8m x 8n (4 n-pairs): per k = 4 LDS.128 + 8 MOV + 32 FFMA2.
// ---------------------------------------------------------------------------
#define XASL 132
__global__ void __launch_bounds__(256)
xg_gemm_kernel(const float* __restrict__ X,
               const float* __restrict__ W,
               const float* __restrict__ bias) {
    __shared__ float As[8 * XASL];   // [k][m] padded
    __shared__ float Bs[8 * 128];    // [k][n]
    const int bm = blockIdx.y * 128;
    const int bn = blockIdx.x * 128;
    const int tid  = threadIdx.x;
    const int lane = tid & 31;
    const int wrp  = tid >> 5;
    const int mG = lane & 3, nG = lane >> 2;
    const int mW = wrp & 3,  nW = wrp >> 2;
    const int mOff = mW * 32 + mG * 8;      // thread's first m in tile
    const int nOff = nW * 64 + nG * 8;      // thread's first n in tile
    const int arow = tid >> 1, acol = (tid & 1) * 4;
    const int brow = tid >> 5, bcol = (tid & 31) * 4;

    ull acc[8][4];
#pragma unroll
    for (int i = 0; i < 8; i++)
#pragma unroll
        for (int j = 0; j < 4; j++) acc[i][j] = 0ull;

    const float* Xp = X + (bm + arow) * D_ + acol;
    const float* Wp = W + brow * G5 + bn + bcol;

    for (int k0 = 0; k0 < D_; k0 += 8) {
        float4 av = *(const float4*)(Xp + k0);
        As[(acol + 0) * XASL + arow] = av.x;
        As[(acol + 1) * XASL + arow] = av.y;
        As[(acol + 2) * XASL + arow] = av.z;
        As[(acol + 3) * XASL + arow] = av.w;
        *(float4*)&Bs[brow * 128 + bcol] = *(const float4*)(Wp + (long)k0 * G5);
        __syncthreads();
#pragma unroll
        for (int k = 0; k < 8; k++) {
            float4 a0 = *(const float4*)(As + k * XASL + mOff);
            float4 a1 = *(const float4*)(As + k * XASL + mOff + 4);
            ull a[8] = {pk(a0.x), pk(a0.y), pk(a0.z), pk(a0.w),
                        pk(a1.x), pk(a1.y), pk(a1.z), pk(a1.w)};
            const ulonglong2* bp = (const ulonglong2*)(Bs + k * 128 + nOff);
            ulonglong2 b01 = bp[0], b23 = bp[1];
            ull b[4] = {b01.x, b01.y, b23.x, b23.y};
#pragma unroll
            for (int i = 0; i < 8; i++)
#pragma unroll
                for (int j = 0; j < 4; j++) acc[i][j] = f2(a[i], b[j], acc[i][j]);
        }
        __syncthreads();
    }

#pragma unroll
    for (int i = 0; i < 8; i++) {
        int m = bm + mOff + i;
        float* o = g_xg + (long)m * G5 + bn + nOff;
#pragma unroll
        for (int j = 0; j < 4; j++) {
            float2 v = up(acc[i][j]);
            o[2 * j]     = v.x + bias[bn + nOff + 2 * j];
            o[2 * j + 1] = v.y + bias[bn + nOff + 2 * j + 1];
        }
    }
}

// ---------------------------------------------------------------------------
// Grid-wide barrier: release-arrive + acquire-spin.
// ---------------------------------------------------------------------------
__device__ __forceinline__ void grid_bar(unsigned target) {
    __syncthreads();
    if (threadIdx.x == 0) {
        asm volatile("red.release.gpu.global.add.u32 [%0], %1;"
                     :: "l"(&g_bar_ctr), "r"(1u) : "memory");
        unsigned v;
        do {
            asm volatile("ld.acquire.gpu.global.u32 %0, [%1];"
                         : "=r"(v) : "l"(&g_bar_ctr) : "memory");
        } while (v < target);
    }
    __syncthreads();
}

// ---------------------------------------------------------------------------
// Scan tile GEMM: block computes 32m x (G x 32u) of Asrc @ W.
// 128 thr (4 warps). Warp w owns m rows [w*8, w*8+8). Lane = 4 mG x 8 uG.
// Thread owns 2m x (G x 2 u-pairs). Per kk:
//   2 LDS.32 A (8-lane broadcast) + G LDS.128 B (contig 128B row)
//   + 2 MOV + 4G FFMA2.   Crossbar ~5cyc/warp << 8G-cyc pipe.
// acc[g*4 + i*2 + p]: i = m sub-row, p = u-pair.
// ---------------------------------------------------------------------------
template <int G>
__device__ __forceinline__ void mm_tile(float* As, float* Bs,
                                        const float* __restrict__ Asrc,
                                        const float* __restrict__ W, int ldw,
                                        int m0, int u0, ull* acc) {
    const int tid  = threadIdx.x;
    const int lane = tid & 31;
    const int wrp  = tid >> 5;
    const int mG = lane & 3, uG = lane >> 2;
    const int aOff = wrp * 8 + mG * 2;      // m offset within tile
    const int mA   = tid >> 2;              // A loader row 0..31
    const int kA   = (tid & 3) * 8;         // A loader k offset

#pragma unroll
    for (int i = 0; i < 4 * G; i++) acc[i] = 0ull;

    // B loader: 2G float4 per thread, tile KT x (G x 32u)
    int  bso[2 * G];
    long bgo[2 * G];
#pragma unroll
    for (int r = 0; r < 2 * G; r++) {
        int fi  = tid + r * NTHR;
        int kk  = fi / (8 * G);
        int rem = fi - kk * 8 * G;
        int g   = rem >> 3;
        int u4  = (rem & 7) * 4;
        bso[r] = (kk * G + g) * BSL + u4;
        bgo[r] = (long)kk * ldw + g * U_ + u0 + u4;
    }
    const float* Ap = Asrc + (m0 + mA) * U_ + kA;

    float4 pa0 = __ldcg((const float4*)(Ap));
    float4 pa1 = __ldcg((const float4*)(Ap + 4));
    float4 pb[2 * G];
#pragma unroll
    for (int r = 0; r < 2 * G; r++)
        pb[r] = __ldg((const float4*)(W + bgo[r]));

    for (int k0 = 0; k0 < U_; k0 += KT) {
        __syncthreads();
        As[(kA + 0) * ASL + mA] = pa0.x;
        As[(kA + 1) * ASL + mA] = pa0.y;
        As[(kA + 2) * ASL + mA] = pa0.z;
        As[(kA + 3) * ASL + mA] = pa0.w;
        As[(kA + 4) * ASL + mA] = pa1.x;
        As[(kA + 5) * ASL + mA] = pa1.y;
        As[(kA + 6) * ASL + mA] = pa1.z;
        As[(kA + 7) * ASL + mA] = pa1.w;
#pragma unroll
        for (int r = 0; r < 2 * G; r++)
            *(float4*)(Bs + bso[r]) = pb[r];
        __syncthreads();
        if (k0 + KT < U_) {
            pa0 = __ldcg((const float4*)(Ap + k0 + KT));
            pa1 = __ldcg((const float4*)(Ap + k0 + KT + 4));
#pragma unroll
            for (int r = 0; r < 2 * G; r++)
                pb[r] = __ldg((const float4*)(W + (long)(k0 + KT) * ldw + bgo[r]));
        }
#pragma unroll 8
        for (int kk = 0; kk < KT; kk++) {
            const float* Ak = As + kk * ASL + aOff;
            ull A0 = pk(Ak[0]);
            ull A1 = pk(Ak[1]);
            const float* Bk = Bs + kk * G * BSL + uG * 4;
#pragma unroll
            for (int g = 0; g < G; g++) {
                ulonglong2 bb = *(const ulonglong2*)(Bk + g * BSL);
                acc[g * 4 + 0] = f2(A0, bb.x, acc[g * 4 + 0]);
                acc[g * 4 + 1] = f2(A0, bb.y, acc[g * 4 + 1]);
                acc[g * 4 + 2] = f2(A1, bb.x, acc[g * 4 + 2]);
                acc[g * 4 + 3] = f2(A1, bb.y, acc[g * 4 + 3]);
            }
        }
    }
}

// ---------------------------------------------------------------------------
// Persistent scan kernel: 128 blocks x 128 threads.
// Block (u0, m0) owns the same 32m x 32u tile in every phase.
// ---------------------------------------------------------------------------
__global__ void __launch_bounds__(NTHR)
scan_kernel(const float* __restrict__ Wr, const float* __restrict__ Wt,
            const float* __restrict__ bias, const float* __restrict__ tbias,
            float* __restrict__ out) {
    __shared__ float As[KT * ASL];
    __shared__ float Bs[KT * 4 * BSL];

    const int u0   = (blockIdx.x & 15) * 32;
    const int m0   = (blockIdx.x >> 4) * 32;
    const int tid  = threadIdx.x;
    const int lane = tid & 31;
    const int wrp  = tid >> 5;
    const int mG = lane & 3, uG = lane >> 2;
    const int mBase = m0 + wrp * 8 + mG * 2;   // thread's first batch row
    const int uBase = u0 + uG * 4;             // thread's first u

    unsigned barno = 0;
    ull acc[16];
    float h1r[2][2][2];   // [i][p][h2]
    float hlr[2][2][2];

    for (int t = 0; t < T_; t++) {
        // ---- phase REC: hg = h @ Wr (4 gates: z, r, hr, l) ----
        mm_tile<4>(As, Bs, g_h, Wr, G4, m0, u0, acc);
#pragma unroll
        for (int i = 0; i < 2; i++) {
            const int b = mBase + i;
            const float* xp = g_xg + ((long)b * T_ + t) * G5;
#pragma unroll
            for (int p = 0; p < 2; p++) {
                float2 vz = up(acc[0  + i * 2 + p]);
                float2 vr = up(acc[4  + i * 2 + p]);
                float2 vh = up(acc[8  + i * 2 + p]);
                float2 vl = up(acc[12 + i * 2 + p]);
#pragma unroll
                for (int h2 = 0; h2 < 2; h2++) {
                    const int u = uBase + p * 2 + h2;
                    float az = h2 ? vz.y : vz.x;
                    float ar = h2 ? vr.y : vr.x;
                    float ah = h2 ? vh.y : vh.x;
                    float al = h2 ? vl.y : vl.x;
                    float z  = hsig(__ldg(xp + u) + az + __ldg(bias + G5 + u));
                    float r  = hsig(__ldg(xp + U_ + u) + ar +
                                    __ldg(bias + G5 + U_ + u));
                    float hh = tanhf(__ldg(xp + 2 * U_ + u) +
                                     r * (ah + __ldg(bias + G5 + 2 * U_ + u)));
                    float hold = __ldcg(g_h + (long)b * U_ + u);
                    float h1 = z * hold + (1.0f - z) * hh;
                    __stcg(g_h1a + (long)b * U_ + u, h1);
                    h1r[i][p][h2] = h1;
                    hlr[i][p][h2] = al + __ldg(bias + G5 + 3 * U_ + u);
                }
            }
        }
        grid_bar(++barno * NBLK);

        // ---- phase T0 ----
        mm_tile<3>(As, Bs, g_h1a, Wt, G3, m0, u0, acc);
#pragma unroll
        for (int i = 0; i < 2; i++) {
            const int b = mBase + i;
#pragma unroll
            for (int p = 0; p < 2; p++) {
                float2 vz = up(acc[0 + i * 2 + p]);
                float2 vr = up(acc[4 + i * 2 + p]);
                float2 vh = up(acc[8 + i * 2 + p]);
#pragma unroll
                for (int h2 = 0; h2 < 2; h2++) {
                    const int u = uBase + p * 2 + h2;
                    float az = h2 ? vz.y : vz.x;
                    float ar = h2 ? vr.y : vr.x;
                    float ah = h2 ? vh.y : vh.x;
                    float zt = hsig(az + __ldg(tbias + u));
                    float rt = hsig(ar + __ldg(tbias + U_ + u));
                    float ht = tanhf(rt * (ah + __ldg(tbias + 2 * U_ + u)));
                    float h1 = zt * h1r[i][p][h2] + (1.0f - zt) * ht;
                    __stcg(g_h1b + (long)b * U_ + u, h1);
                    h1r[i][p][h2] = h1;
                }
            }
        }
        grid_bar(++barno * NBLK);

        // ---- phase T1 + final combine ----
        mm_tile<3>(As, Bs, g_h1b, Wt + (long)U_ * G3, G3, m0, u0, acc);
#pragma unroll
        for (int i = 0; i < 2; i++) {
            const int b = mBase + i;
            const float* xp = g_xg + ((long)b * T_ + t) * G5;
#pragma unroll
            for (int p = 0; p < 2; p++) {
                float2 vz = up(acc[0 + i * 2 + p]);
                float2 vr = up(acc[4 + i * 2 + p]);
                float2 vh = up(acc[8 + i * 2 + p]);
#pragma unroll
                for (int h2 = 0; h2 < 2; h2++) {
                    const int u = uBase + p * 2 + h2;
                    float az = h2 ? vz.y : vz.x;
                    float ar = h2 ? vr.y : vr.x;
                    float ah = h2 ? vh.y : vh.x;
                    float zt = hsig(az + __ldg(tbias + G3 + u));
                    float rt = hsig(ar + __ldg(tbias + G3 + U_ + u));
                    float ht = tanhf(rt * (ah + __ldg(tbias + G3 + 2 * U_ + u)));
                    float h1 = zt * h1r[i][p][h2] + (1.0f - zt) * ht;
                    float l  = hsig(__ldg(xp + 3 * U_ + u) + hlr[i][p][h2]);
                    float ho = l * h1 + (1.0f - l) * tanhf(__ldg(xp + 4 * U_ + u));
                    __stcg(g_h + (long)b * U_ + u, ho);
                    out[((long)b * T_ + t) * U_ + u] = ho;
                }
            }
        }
        grid_bar(++barno * NBLK);
    }
}

// ---------------------------------------------------------------------------
extern "C" void kernel_launch(void* const* d_in, const int* in_sizes, int n_in,
                              void* d_out, int out_size) {
    (void)in_sizes; (void)n_in; (void)out_size;
    const float* x      = (const float*)d_in[0];
    const float* h0     = (const float*)d_in[1];
    const float* kernel = (const float*)d_in[2];
    const float* Wr     = (const float*)d_in[3];
    const float* Wt     = (const float*)d_in[4];
    const float* bias   = (const float*)d_in[5];
    const float* tbias  = (const float*)d_in[6];
    float* out = (float*)d_out;

    init_h_kernel<<<(B_ * U_ + 255) / 256, 256>>>(h0);
    xg_gemm_kernel<<<dim3(G5 / 128, (B_ * T_) / 128), 256>>>(x, kernel, bias);
    scan_kernel<<<NBLK, NTHR>>>(Wr, Wt, bias, tbias, out);
}

// round 9
// speedup vs baseline: 1.4574x; 1.0429x over previous
#include <cuda_runtime.h>
#include <math.h>

// Problem constants
#define B_ 256
#define T_ 128
#define D_ 256
#define U_ 512
#define G5 2560   // 5*U
#define G4 2048   // 4*U
#define G3 1536   // 3*U

#define NBLK 128
#define NTHR 256          // scan threads per block (8 warps, 2 K-split sets)
#define KT2 64            // staged K chunk
#define ASTR 68           // A smem stride ([m][k] row stride, floats)
#define BSL 32            // B smem stride per (kk,gate): exactly 128B

// Scratch (device globals: allocation-free per harness rules)
__device__ float g_xg[(long)B_ * T_ * G5];
__device__ float g_h [B_ * U_];
__device__ float g_h1a[B_ * U_];
__device__ float g_h1b[B_ * U_];
__device__ unsigned g_bar_ctr;

__device__ __forceinline__ float hsig(float x) {
    return fminf(fmaxf(0.2f * x + 0.5f, 0.0f), 1.0f);
}

typedef unsigned long long ull;
__device__ __forceinline__ ull pk(float x) {
    ull r; asm("mov.b64 %0, {%1, %1};" : "=l"(r) : "f"(x)); return r;
}
__device__ __forceinline__ ull f2(ull a, ull b, ull c) {
    ull d; asm("fma.rn.f32x2 %0, %1, %2, %3;" : "=l"(d) : "l"(a), "l"(b), "l"(c));
    return d;
}
__device__ __forceinline__ ull a2(ull a, ull b) {
    ull d; asm("add.rn.f32x2 %0, %1, %2;" : "=l"(d) : "l"(a), "l"(b));
    return d;
}
__device__ __forceinline__ float2 up(ull v) {
    float2 r; asm("mov.b64 {%0, %1}, %2;" : "=f"(r.x), "=f"(r.y) : "l"(v));
    return r;
}

// ---------------------------------------------------------------------------
__global__ void init_h_kernel(const float* __restrict__ h0) {
    int i = blockIdx.x * blockDim.x + threadIdx.x;
    if (i < B_ * U_) g_h[i] = h0[i];
    if (i == 0) g_bar_ctr = 0;
}

// ---------------------------------------------------------------------------
// xg = x @ kernel + bias[0].  (known-good R8 version)
// ---------------------------------------------------------------------------
#define XASL 132
__global__ void __launch_bounds__(256)
xg_gemm_kernel(const float* __restrict__ X,
               const float* __restrict__ W,
               const float* __restrict__ bias) {
    __shared__ float As[8 * XASL];
    __shared__ float Bs[8 * 128];
    const int bm = blockIdx.y * 128;
    const int bn = blockIdx.x * 128;
    const int tid  = threadIdx.x;
    const int lane = tid & 31;
    const int wrp  = tid >> 5;
    const int mG = lane & 3, nG = lane >> 2;
    const int mW = wrp & 3,  nW = wrp >> 2;
    const int mOff = mW * 32 + mG * 8;
    const int nOff = nW * 64 + nG * 8;
    const int arow = tid >> 1, acol = (tid & 1) * 4;
    const int brow = tid >> 5, bcol = (tid & 31) * 4;

    ull acc[8][4];
#pragma unroll
    for (int i = 0; i < 8; i++)
#pragma unroll
        for (int j = 0; j < 4; j++) acc[i][j] = 0ull;

    const float* Xp = X + (bm + arow) * D_ + acol;
    const float* Wp = W + brow * G5 + bn + bcol;

    for (int k0 = 0; k0 < D_; k0 += 8) {
        float4 av = *(const float4*)(Xp + k0);
        As[(acol + 0) * XASL + arow] = av.x;
        As[(acol + 1) * XASL + arow] = av.y;
        As[(acol + 2) * XASL + arow] = av.z;
        As[(acol + 3) * XASL + arow] = av.w;
        *(float4*)&Bs[brow * 128 + bcol] = *(const float4*)(Wp + (long)k0 * G5);
        __syncthreads();
#pragma unroll
        for (int k = 0; k < 8; k++) {
            float4 a0 = *(const float4*)(As + k * XASL + mOff);
            float4 a1 = *(const float4*)(As + k * XASL + mOff + 4);
            ull a[8] = {pk(a0.x), pk(a0.y), pk(a0.z), pk(a0.w),
                        pk(a1.x), pk(a1.y), pk(a1.z), pk(a1.w)};
            const ulonglong2* bp = (const ulonglong2*)(Bs + k * 128 + nOff);
            ulonglong2 b01 = bp[0], b23 = bp[1];
            ull b[4] = {b01.x, b01.y, b23.x, b23.y};
#pragma unroll
            for (int i = 0; i < 8; i++)
#pragma unroll
                for (int j = 0; j < 4; j++) acc[i][j] = f2(a[i], b[j], acc[i][j]);
        }
        __syncthreads();
    }

#pragma unroll
    for (int i = 0; i < 8; i++) {
        int m = bm + mOff + i;
        float* o = g_xg + (long)m * G5 + bn + nOff;
#pragma unroll
        for (int j = 0; j < 4; j++) {
            float2 v = up(acc[i][j]);
            o[2 * j]     = v.x + bias[bn + nOff + 2 * j];
            o[2 * j + 1] = v.y + bias[bn + nOff + 2 * j + 1];
        }
    }
}

// ---------------------------------------------------------------------------
// Grid-wide barrier: release-arrive + acquire-spin.
// ---------------------------------------------------------------------------
__device__ __forceinline__ void grid_bar(unsigned target) {
    __syncthreads();
    if (threadIdx.x == 0) {
        asm volatile("red.release.gpu.global.add.u32 [%0], %1;"
                     :: "l"(&g_bar_ctr), "r"(1u) : "memory");
        unsigned v;
        do {
            asm volatile("ld.acquire.gpu.global.u32 %0, [%1];"
                         : "=r"(v) : "l"(&g_bar_ctr) : "memory");
        } while (v < target);
    }
    __syncthreads();
}

// ---------------------------------------------------------------------------
// K-split tile GEMM: 256 thr, 8 warps as 2 sets x 4 warps.
// Block tile: 32m x (G x 32u). Warp-set S handles kk = S*32 + [0,32) of each
// staged KT2=64 chunk; both sets produce partial sums for the SAME outputs.
// Warp w4 (wrp&3) owns m rows [w4*8, w4*8+8); lane = 4 mG x 8 uG.
// Per kk per warp: 2 LDS.32 A (broadcast) + G LDS.128 B + 2 MOV + 4G FFMA2.
// ---------------------------------------------------------------------------
template <int G>
__device__ __forceinline__ void mm_tile(float* As, float* Bs,
                                        const float* __restrict__ Asrc,
                                        const float* __restrict__ W, int ldw,
                                        int m0, int u0, ull* acc) {
    const int tid  = threadIdx.x;
    const int lane = tid & 31;
    const int wrp  = tid >> 5;
    const int S    = wrp >> 2;          // K-split set
    const int w4   = wrp & 3;
    const int mG = lane & 3, uG = lane >> 2;
    const int aOff = w4 * 8 + mG * 2;   // m offset within tile
    const int mA   = tid >> 3;          // A loader: m row 0..31
    const int kA   = (tid & 7) * 8;     // A loader: k offset 0..56

#pragma unroll
    for (int i = 0; i < 4 * G; i++) acc[i] = 0ull;

    // B loader: 2G float4 per thread, tile KT2 x (G x 32u)
    int  bso[2 * G];
    long bgo[2 * G];
#pragma unroll
    for (int r = 0; r < 2 * G; r++) {
        int fi  = tid + r * NTHR;
        int kk  = fi / (8 * G);
        int rem = fi - kk * 8 * G;
        int g   = rem >> 3;
        int u4  = (rem & 7) * 4;
        bso[r] = (kk * G + g) * BSL + u4;
        bgo[r] = (long)kk * ldw + g * U_ + u0 + u4;
    }
    const float* Ap = Asrc + (m0 + mA) * U_ + kA;

    float4 pa0 = __ldcg((const float4*)(Ap));
    float4 pa1 = __ldcg((const float4*)(Ap + 4));
    float4 pb[2 * G];
#pragma unroll
    for (int r = 0; r < 2 * G; r++)
        pb[r] = __ldg((const float4*)(W + bgo[r]));

    for (int k0 = 0; k0 < U_; k0 += KT2) {
        __syncthreads();
        *(float4*)(As + mA * ASTR + kA)     = pa0;
        *(float4*)(As + mA * ASTR + kA + 4) = pa1;
#pragma unroll
        for (int r = 0; r < 2 * G; r++)
            *(float4*)(Bs + bso[r]) = pb[r];
        __syncthreads();
        if (k0 + KT2 < U_) {
            pa0 = __ldcg((const float4*)(Ap + k0 + KT2));
            pa1 = __ldcg((const float4*)(Ap + k0 + KT2 + 4));
#pragma unroll
            for (int r = 0; r < 2 * G; r++)
                pb[r] = __ldg((const float4*)(W + (long)(k0 + KT2) * ldw + bgo[r]));
        }
        const float* A0p = As + (aOff + 0) * ASTR + S * 32;
        const float* A1p = As + (aOff + 1) * ASTR + S * 32;
        const float* Bbase = Bs + (S * 32) * G * BSL + uG * 4;
#pragma unroll 8
        for (int kk2 = 0; kk2 < 32; kk2++) {
            ull A0 = pk(A0p[kk2]);
            ull A1 = pk(A1p[kk2]);
            const float* Bk = Bbase + kk2 * G * BSL;
#pragma unroll
            for (int g = 0; g < G; g++) {
                ulonglong2 bb = *(const ulonglong2*)(Bk + g * BSL);
                acc[g * 4 + 0] = f2(A0, bb.x, acc[g * 4 + 0]);
                acc[g * 4 + 1] = f2(A0, bb.y, acc[g * 4 + 1]);
                acc[g * 4 + 2] = f2(A1, bb.x, acc[g * 4 + 2]);
                acc[g * 4 + 3] = f2(A1, bb.y, acc[g * 4 + 3]);
            }
        }
    }
}

// Cross-set reduction: set 1 dumps partials, set 0 accumulates.
// Returns with valid full acc in threads tid < 128. Red overlays Bs.
template <int G>
__device__ __forceinline__ void k_reduce(ull* Red, ull* acc) {
    const int tid = threadIdx.x;
    __syncthreads();                      // all compute done with Bs
    if (tid >= 128) {
#pragma unroll
        for (int j = 0; j < 4 * G; j++) Red[(tid - 128) * 17 + j] = acc[j];
    }
    __syncthreads();
    if (tid < 128) {
#pragma unroll
        for (int j = 0; j < 4 * G; j++) acc[j] = a2(acc[j], Red[tid * 17 + j]);
    }
}

// ---------------------------------------------------------------------------
// Persistent scan kernel: 128 blocks x 256 threads.
// Epilogues run on tid < 128 (same tile ownership as R8's 128-thread layout).
// ---------------------------------------------------------------------------
__global__ void __launch_bounds__(NTHR)
scan_kernel(const float* __restrict__ Wr, const float* __restrict__ Wt,
            const float* __restrict__ bias, const float* __restrict__ tbias,
            float* __restrict__ out) {
    __shared__ __align__(16) char pool[32 * ASTR * 4 + KT2 * 4 * BSL * 4];
    float* As = (float*)pool;                       // 32 x ASTR floats
    float* Bs = (float*)(pool + 32 * ASTR * 4);     // KT2 x 4 x BSL floats
    ull*  Red = (ull*)Bs;                           // 128 x 17 ull overlay

    const int u0   = (blockIdx.x & 15) * 32;
    const int m0   = (blockIdx.x >> 4) * 32;
    const int tid  = threadIdx.x;
    const int lane = tid & 31;
    const int wrp  = tid >> 5;           // epilogue uses wrp 0..3 (tid<128)
    const int mG = lane & 3, uG = lane >> 4 == 0 ? (lane >> 2) : (lane >> 2);
    const int mBase = m0 + (wrp & 3) * 8 + mG * 2;
    const int uBase = u0 + (lane >> 2) * 4;

    unsigned barno = 0;
    ull acc[16];
    float h1r[2][2][2];   // [i][p][h2]  (valid in tid<128)
    float hlr[2][2][2];

    for (int t = 0; t < T_; t++) {
        // ---- phase REC: hg = h @ Wr (4 gates: z, r, hr, l) ----
        mm_tile<4>(As, Bs, g_h, Wr, G4, m0, u0, acc);
        k_reduce<4>(Red, acc);
        if (tid < 128) {
#pragma unroll
            for (int i = 0; i < 2; i++) {
                const int b = mBase + i;
                const float* xp = g_xg + ((long)b * T_ + t) * G5;
#pragma unroll
                for (int p = 0; p < 2; p++) {
                    float2 vz = up(acc[0  + i * 2 + p]);
                    float2 vr = up(acc[4  + i * 2 + p]);
                    float2 vh = up(acc[8  + i * 2 + p]);
                    float2 vl = up(acc[12 + i * 2 + p]);
#pragma unroll
                    for (int h2 = 0; h2 < 2; h2++) {
                        const int u = uBase + p * 2 + h2;
                        float az = h2 ? vz.y : vz.x;
                        float ar = h2 ? vr.y : vr.x;
                        float ah = h2 ? vh.y : vh.x;
                        float al = h2 ? vl.y : vl.x;
                        float z  = hsig(__ldg(xp + u) + az + __ldg(bias + G5 + u));
                        float r  = hsig(__ldg(xp + U_ + u) + ar +
                                        __ldg(bias + G5 + U_ + u));
                        float hh = tanhf(__ldg(xp + 2 * U_ + u) +
                                         r * (ah + __ldg(bias + G5 + 2 * U_ + u)));
                        float hold = __ldcg(g_h + (long)b * U_ + u);
                        float h1 = z * hold + (1.0f - z) * hh;
                        __stcg(g_h1a + (long)b * U_ + u, h1);
                        h1r[i][p][h2] = h1;
                        hlr[i][p][h2] = al + __ldg(bias + G5 + 3 * U_ + u);
                    }
                }
            }
        }
        grid_bar(++barno * NBLK);

        // ---- phase T0 ----
        mm_tile<3>(As, Bs, g_h1a, Wt, G3, m0, u0, acc);
        k_reduce<3>(Red, acc);
        if (tid < 128) {
#pragma unroll
            for (int i = 0; i < 2; i++) {
                const int b = mBase + i;
#pragma unroll
                for (int p = 0; p < 2; p++) {
                    float2 vz = up(acc[0 + i * 2 + p]);
                    float2 vr = up(acc[4 + i * 2 + p]);
                    float2 vh = up(acc[8 + i * 2 + p]);
#pragma unroll
                    for (int h2 = 0; h2 < 2; h2++) {
                        const int u = uBase + p * 2 + h2;
                        float az = h2 ? vz.y : vz.x;
                        float ar = h2 ? vr.y : vr.x;
                        float ah = h2 ? vh.y : vh.x;
                        float zt = hsig(az + __ldg(tbias + u));
                        float rt = hsig(ar + __ldg(tbias + U_ + u));
                        float ht = tanhf(rt * (ah + __ldg(tbias + 2 * U_ + u)));
                        float h1 = zt * h1r[i][p][h2] + (1.0f - zt) * ht;
                        __stcg(g_h1b + (long)b * U_ + u, h1);
                        h1r[i][p][h2] = h1;
                    }
                }
            }
        }
        grid_bar(++barno * NBLK);

        // ---- phase T1 + final combine ----
        mm_tile<3>(As, Bs, g_h1b, Wt + (long)U_ * G3, G3, m0, u0, acc);
        k_reduce<3>(Red, acc);
        if (tid < 128) {
#pragma unroll
            for (int i = 0; i < 2; i++) {
                const int b = mBase + i;
                const float* xp = g_xg + ((long)b * T_ + t) * G5;
#pragma unroll
                for (int p = 0; p < 2; p++) {
                    float2 vz = up(acc[0 + i * 2 + p]);
                    float2 vr = up(acc[4 + i * 2 + p]);
                    float2 vh = up(acc[8 + i * 2 + p]);
#pragma unroll
                    for (int h2 = 0; h2 < 2; h2++) {
                        const int u = uBase + p * 2 + h2;
                        float az = h2 ? vz.y : vz.x;
                        float ar = h2 ? vr.y : vr.x;
                        float ah = h2 ? vh.y : vh.x;
                        float zt = hsig(az + __ldg(tbias + G3 + u));
                        float rt = hsig(ar + __ldg(tbias + G3 + U_ + u));
                        float ht = tanhf(rt * (ah + __ldg(tbias + G3 + 2 * U_ + u)));
                        float h1 = zt * h1r[i][p][h2] + (1.0f - zt) * ht;
                        float l  = hsig(__ldg(xp + 3 * U_ + u) + hlr[i][p][h2]);
                        float ho = l * h1 +
                                   (1.0f - l) * tanhf(__ldg(xp + 4 * U_ + u));
                        __stcg(g_h + (long)b * U_ + u, ho);
                        out[((long)b * T_ + t) * U_ + u] = ho;
                    }
                }
            }
        }
        grid_bar(++barno * NBLK);
    }
}

// ---------------------------------------------------------------------------
extern "C" void kernel_launch(void* const* d_in, const int* in_sizes, int n_in,
                              void* d_out, int out_size) {
    (void)in_sizes; (void)n_in; (void)out_size;
    const float* x      = (const float*)d_in[0];
    const float* h0     = (const float*)d_in[1];
    const float* kernel = (const float*)d_in[2];
    const float* Wr     = (const float*)d_in[3];
    const float* Wt     = (const float*)d_in[4];
    const float* bias   = (const float*)d_in[5];
    const float* tbias  = (const float*)d_in[6];
    float* out = (float*)d_out;

    init_h_kernel<<<(B_ * U_ + 255) / 256, 256>>>(h0);
    xg_gemm_kernel<<<dim3(G5 / 128, (B_ * T_) / 128), 256>>>(x, kernel, bias);
    scan_kernel<<<NBLK, NTHR>>>(Wr, Wt, bias, tbias, out);
}